// round 17
// baseline (speedup 1.0000x reference)
#include <cuda_runtime.h>
#include <cuda_bf16.h>
#include <cstdint>

#define KDIM   256
#define NF     64
#define N1R    8192
#define KH     5
#define BM     16
#define CK     64               // K chunk
#define NCHUNK (KDIM / CK)      // 4
#define NTHR   256

static __device__ __forceinline__ uint32_t smem_cast(const void* p) {
    return (uint32_t)__cvta_generic_to_shared(p);
}
static __device__ __forceinline__ void ldsm_x4(uint32_t* r, uint32_t addr) {
    asm volatile("ldmatrix.sync.aligned.m8n8.x4.shared.b16 {%0,%1,%2,%3}, [%4];"
                 : "=r"(r[0]), "=r"(r[1]), "=r"(r[2]), "=r"(r[3]) : "r"(addr));
}
static __device__ __forceinline__ void ldsm_x2_t(uint32_t* r, uint32_t addr) {
    asm volatile("ldmatrix.sync.aligned.m8n8.x2.trans.shared.b16 {%0,%1}, [%2];"
                 : "=r"(r[0]), "=r"(r[1]) : "r"(addr));
}
static __device__ __forceinline__ void mma_bf16(float* d, const uint32_t* a,
                                                uint32_t b0, uint32_t b1) {
    asm volatile("mma.sync.aligned.m16n8k16.row.col.f32.bf16.bf16.f32 "
                 "{%0,%1,%2,%3}, {%4,%5,%6,%7}, {%8,%9}, {%0,%1,%2,%3};"
                 : "+f"(d[0]), "+f"(d[1]), "+f"(d[2]), "+f"(d[3])
                 : "r"(a[0]), "r"(a[1]), "r"(a[2]), "r"(a[3]), "r"(b0), "r"(b1));
}

// ---------------------------------------------------------------------------
// SINGLE fused kernel: out = G @ x @ W + 5*bias
// (floor(softmax/1000) == 0 identically => e == G; G rows = 5 ones at qq.)
// s = gather-sum of x rows (fp32) -> Markidis bf16 split -> HMMA (3 passes:
// hi*hi + hi*lo + lo*hi, fp32 accum; rel ~4e-6).
//
// R16 lesson: occupancy was GRID-limited (256 CTAs = 1.73/SM) -- reg diets
// can't help. Here: BM=16 -> 512 CTAs, 3.46 avg CTAs/SM, ~27 warps/SM.
// Warp tile m16 x n8 (n0 = wid*8); A frag shared by all 8 warps (smem pipe
// had headroom); B read via ldsm x2.trans = first half of the validated
// x4.trans pattern. pa[5] prefetch keeps regs ~60 -> launch_bounds(256,4).
// All R14-proven structure retained (prefetch ISSUE, 2 bars/chunk).
// ---------------------------------------------------------------------------
__global__ __launch_bounds__(NTHR, 4) void fused_tc_kernel(const float* __restrict__ x,
                                                           const int* __restrict__ qq,
                                                           const float* __restrict__ w,
                                                           const float* __restrict__ bias,
                                                           float* __restrict__ out) {
    __shared__ __nv_bfloat16 Ahi[BM][72], Alo[BM][72];   // s chunk [16 x 64]
    __shared__ __nv_bfloat16 Bhi[CK][72], Blo[CK][72];   // W chunk [64 x 64]
    __shared__ int qs[BM * KH];                          // 80 indices

    const int tid  = threadIdx.x;
    const int wid  = tid >> 5;
    const int lane = tid & 31;
    const int r0   = blockIdx.x * BM;
    const int n0   = wid * 8;

    if (tid < BM * KH) qs[tid] = qq[r0 * KH + tid];
    __syncthreads();

    const float4* x4 = (const float4*)x;   // row stride 64 float4
    const float4* w4 = (const float4*)w;   // row stride 16 float4

    // A staging: 256 slots (16 rows x 16 float4), exactly 1 per thread
    const int arow = tid >> 4;
    const int ac4  = tid & 15;
    int qi[KH];
    #pragma unroll
    for (int t = 0; t < KH; t++) qi[t] = qs[arow * KH + t];

    float4 pa[KH];
    float  d[4] = {};

    const int a_row = lane & 15;
    const int a_col = (lane >> 4) << 3;
    const int b_row = lane & 15;           // x2.trans: lanes 0-15 supply addrs

#define ISSUE(c)                                                               \
    {                                                                          \
        const float4* xp = x4 + (c) * 16 + ac4;                                \
        _Pragma("unroll")                                                      \
        for (int t = 0; t < KH; t++) pa[t] = xp[(size_t)qi[t] * 64];           \
    }

    ISSUE(0);

    #pragma unroll 1
    for (int c = 0; c < NCHUNK; c++) {
        // ---- convert prefetched gathers -> A tile ----
        {
            float sx = pa[0].x + pa[1].x + pa[2].x + pa[3].x + pa[4].x;
            float sy = pa[0].y + pa[1].y + pa[2].y + pa[3].y + pa[4].y;
            float sz = pa[0].z + pa[1].z + pa[2].z + pa[3].z + pa[4].z;
            float sw = pa[0].w + pa[1].w + pa[2].w + pa[3].w + pa[4].w;
            float hx = __bfloat162float(__float2bfloat16_rn(sx));
            float hy = __bfloat162float(__float2bfloat16_rn(sy));
            float hz = __bfloat162float(__float2bfloat16_rn(sz));
            float hw = __bfloat162float(__float2bfloat16_rn(sw));
            *(__nv_bfloat162*)&Ahi[arow][ac4 * 4 + 0] = __floats2bfloat162_rn(hx, hy);
            *(__nv_bfloat162*)&Ahi[arow][ac4 * 4 + 2] = __floats2bfloat162_rn(hz, hw);
            *(__nv_bfloat162*)&Alo[arow][ac4 * 4 + 0] = __floats2bfloat162_rn(sx - hx, sy - hy);
            *(__nv_bfloat162*)&Alo[arow][ac4 * 4 + 2] = __floats2bfloat162_rn(sz - hz, sw - hw);
        }
        // ---- stage B chunk [64 x 64] (1024 float4 slots, 4 per thread) ----
        #pragma unroll
        for (int j = 0; j < 4; j++) {
            int idx = tid + j * NTHR;
            int kk = idx >> 4, c4 = idx & 15;
            float4 v = w4[(size_t)(c * CK + kk) * 16 + c4];
            float hx = __bfloat162float(__float2bfloat16_rn(v.x));
            float hy = __bfloat162float(__float2bfloat16_rn(v.y));
            float hz = __bfloat162float(__float2bfloat16_rn(v.z));
            float hw = __bfloat162float(__float2bfloat16_rn(v.w));
            *(__nv_bfloat162*)&Bhi[kk][c4 * 4 + 0] = __floats2bfloat162_rn(hx, hy);
            *(__nv_bfloat162*)&Bhi[kk][c4 * 4 + 2] = __floats2bfloat162_rn(hz, hw);
            *(__nv_bfloat162*)&Blo[kk][c4 * 4 + 0] = __floats2bfloat162_rn(v.x - hx, v.y - hy);
            *(__nv_bfloat162*)&Blo[kk][c4 * 4 + 2] = __floats2bfloat162_rn(v.z - hz, v.w - hw);
        }
        __syncthreads();

        // ---- prefetch next chunk's gathers: latency overlaps mma ----
        if (c < NCHUNK - 1) ISSUE(c + 1);

        // ---- mma: 4 k16 steps, warp tile m16 x n8 ----
        #pragma unroll
        for (int ko = 0; ko < CK; ko += 16) {
            uint32_t ah[4], al[4], bh[2], bl[2];
            ldsm_x4(ah, smem_cast(&Ahi[a_row][ko + a_col]));
            ldsm_x4(al, smem_cast(&Alo[a_row][ko + a_col]));
            ldsm_x2_t(bh, smem_cast(&Bhi[ko + b_row][n0]));
            ldsm_x2_t(bl, smem_cast(&Blo[ko + b_row][n0]));
            mma_bf16(d, ah, bh[0], bh[1]);   // hi*hi
            mma_bf16(d, ah, bl[0], bl[1]);   // hi*lo
            mma_bf16(d, al, bh[0], bh[1]);   // lo*hi
        }
        __syncthreads();
    }
#undef ISSUE

    // ---- epilogue: frag -> out with + 5*bias ----
    const int fr  = lane >> 2;
    const int fc2 = (lane & 3) * 2;
    {
        int col = n0 + fc2;
        float2 bv = *(const float2*)&bias[col];
        int rowA = r0 + fr;
        int rowB = rowA + 8;
        *(float2*)&out[(size_t)rowA * NF + col] =
            make_float2(d[0] + 5.0f * bv.x, d[1] + 5.0f * bv.y);
        *(float2*)&out[(size_t)rowB * NF + col] =
            make_float2(d[2] + 5.0f * bv.x, d[3] + 5.0f * bv.y);
    }
}

// ---------------------------------------------------------------------------
// Inputs (metadata order):
//   0: x [10000,256] f32, 1: G (unused), 2: weight [256,64] f32,
//   3: a (unused — attention branch identically zero), 4: bias [64] f32,
//   5: qq [40960] i32, 6: rows (unused)
// output: [8192,64] f32
// ---------------------------------------------------------------------------
extern "C" void kernel_launch(void* const* d_in, const int* in_sizes, int n_in,
                              void* d_out, int out_size) {
    const float* x    = (const float*)d_in[0];
    const float* w    = (const float*)d_in[2];
    const float* bias = (const float*)d_in[4];
    const int*   qq   = (const int*)d_in[5];
    float*       out  = (float*)d_out;

    fused_tc_kernel<<<N1R / BM, NTHR>>>(x, qq, w, bias, out);
}